// round 1
// baseline (speedup 1.0000x reference)
#include <cuda_runtime.h>
#include <math.h>

// Problem constants
#define M_ROWS   4096      // B*S
#define NTDIM    1024
#define NGROUP   64        // B*heads
#define DPH      64
#define SEQ      1024      // rows per head-group after flat reshape
#define ATT_SCALE 0.03125f // 1024^-0.5
#define LNEPS    1e-5f

// Scratch (allocation-free rule: __device__ globals)
__device__ float g_q[M_ROWS * NTDIM];
__device__ float g_k[M_ROWS * NTDIM];
__device__ float g_v[M_ROWS * NTDIM];
__device__ float g_ctx[M_ROWS * NTDIM];

// ---------------------------------------------------------------------------
// Kernel 0: zero the at_sum_sum region of d_out (poisoned 0xAA each replay)
// ---------------------------------------------------------------------------
__global__ void zero_sums_kernel(float* __restrict__ sums) {
    sums[blockIdx.x * 256 + threadIdx.x] = 0.0f;
}

// ---------------------------------------------------------------------------
// Kernel 1: QKV projection.  C = X * W^T + b   (X [4096,1024], W [1024,1024])
// grid (8 nblk, 32 mblk, 3 matrices), 256 threads, 128x128 tile, 8x8/thread.
// ---------------------------------------------------------------------------
__global__ __launch_bounds__(256) void qkv_kernel(
    const float* __restrict__ x,
    const float* __restrict__ Wq, const float* __restrict__ bq,
    const float* __restrict__ Wk, const float* __restrict__ bk,
    const float* __restrict__ Wv, const float* __restrict__ bv)
{
    const float* W; const float* bias; float* out;
    if (blockIdx.z == 0)      { W = Wq; bias = bq; out = g_q; }
    else if (blockIdx.z == 1) { W = Wk; bias = bk; out = g_k; }
    else                      { W = Wv; bias = bv; out = g_v; }

    __shared__ float As[16][132];   // k-major: As[k][m]
    __shared__ float Bs[16][132];   // k-major: Bs[k][n]

    const int m0 = blockIdx.y * 128;
    const int n0 = blockIdx.x * 128;
    const int t  = threadIdx.x;
    const int tx = t & 15;          // 0..15 -> n frag
    const int ty = t >> 4;          // 0..15 -> m frag

    const int lrow = t >> 2;        // 0..63
    const int lk4  = (t & 3) * 4;   // 0,4,8,12

    float acc[8][8];
    #pragma unroll
    for (int i = 0; i < 8; i++)
        #pragma unroll
        for (int j = 0; j < 8; j++) acc[i][j] = 0.0f;

    for (int k0 = 0; k0 < NTDIM; k0 += 16) {
        #pragma unroll
        for (int h = 0; h < 2; h++) {
            int row = lrow + h * 64;
            float4 va = *reinterpret_cast<const float4*>(&x[(size_t)(m0 + row) * NTDIM + k0 + lk4]);
            As[lk4 + 0][row] = va.x; As[lk4 + 1][row] = va.y;
            As[lk4 + 2][row] = va.z; As[lk4 + 3][row] = va.w;
            float4 vb = *reinterpret_cast<const float4*>(&W[(size_t)(n0 + row) * NTDIM + k0 + lk4]);
            Bs[lk4 + 0][row] = vb.x; Bs[lk4 + 1][row] = vb.y;
            Bs[lk4 + 2][row] = vb.z; Bs[lk4 + 3][row] = vb.w;
        }
        __syncthreads();

        #pragma unroll 8
        for (int k = 0; k < 16; k++) {
            float4 a0 = *reinterpret_cast<const float4*>(&As[k][ty * 4]);
            float4 a1 = *reinterpret_cast<const float4*>(&As[k][64 + ty * 4]);
            float4 b0 = *reinterpret_cast<const float4*>(&Bs[k][tx * 4]);
            float4 b1 = *reinterpret_cast<const float4*>(&Bs[k][64 + tx * 4]);
            float a[8] = {a0.x, a0.y, a0.z, a0.w, a1.x, a1.y, a1.z, a1.w};
            float b[8] = {b0.x, b0.y, b0.z, b0.w, b1.x, b1.y, b1.z, b1.w};
            #pragma unroll
            for (int i = 0; i < 8; i++)
                #pragma unroll
                for (int j = 0; j < 8; j++) acc[i][j] += a[i] * b[j];
        }
        __syncthreads();
    }

    #pragma unroll
    for (int ih = 0; ih < 2; ih++) {
        #pragma unroll
        for (int r = 0; r < 4; r++) {
            int m = m0 + ih * 64 + ty * 4 + r;
            #pragma unroll
            for (int jh = 0; jh < 2; jh++) {
                int n = n0 + jh * 64 + tx * 4;
                float4 o;
                o.x = acc[ih * 4 + r][jh * 4 + 0] + bias[n + 0];
                o.y = acc[ih * 4 + r][jh * 4 + 1] + bias[n + 1];
                o.z = acc[ih * 4 + r][jh * 4 + 2] + bias[n + 2];
                o.w = acc[ih * 4 + r][jh * 4 + 3] + bias[n + 3];
                *reinterpret_cast<float4*>(&out[(size_t)m * NTDIM + n]) = o;
            }
        }
    }
}

// ---------------------------------------------------------------------------
// Kernel 2: attention per (row-block, head-group). Two-pass softmax so the
// normalized column sums (at_sum_sum) and context can stream over K/V tiles.
// ---------------------------------------------------------------------------
// dynamic smem layout (floats)
#define SM_QST   0                     // [64][132]  k-major swizzled Q
#define SM_KST   8448                  // [64][132]
#define SM_VS    16896                 // [128][68]  row-major V
#define SM_PST   25600                 // [128][132] col-major swizzled P
#define SM_RS    42496                 // [128] row sums
#define SM_CS    42624                 // [128] col sums
#define ATT_SMEM_FLOATS 42752
#define ATT_SMEM_BYTES  (ATT_SMEM_FLOATS * 4)

__device__ __forceinline__ int swz4(int idx) { return ((idx >> 2) & 7) << 2; }

__global__ __launch_bounds__(256) void attn_kernel(float* __restrict__ sums)
{
    extern __shared__ float sm[];
    float* QsT = sm + SM_QST;
    float* KsT = sm + SM_KST;
    float* Vs  = sm + SM_VS;
    float* PsT = sm + SM_PST;
    float* rs  = sm + SM_RS;
    float* cs  = sm + SM_CS;

    const int g  = blockIdx.y;        // head-group 0..63
    const int ib = blockIdx.x;        // row block 0..7
    const float* __restrict__ Qh = g_q + (size_t)g * (SEQ * DPH);
    const float* __restrict__ Kh = g_k + (size_t)g * (SEQ * DPH);
    const float* __restrict__ Vh = g_v + (size_t)g * (SEQ * DPH);

    const int t  = threadIdx.x;
    const int tx = t & 15;
    const int ty = t >> 4;
    const int r0 = ty * 4;
    const int c0 = tx * 4;

    // stage Q block (rows ib*128..+127) k-major with swizzle
    #pragma unroll
    for (int it = 0; it < 8; it++) {
        int fid = t + it * 256;
        int row = fid >> 4;
        int d   = (fid & 15) * 4;
        float4 v = *reinterpret_cast<const float4*>(&Qh[(size_t)(ib * 128 + row) * DPH + d]);
        QsT[(d + 0) * 132 + (row ^ swz4(d + 0))] = v.x;
        QsT[(d + 1) * 132 + (row ^ swz4(d + 1))] = v.y;
        QsT[(d + 2) * 132 + (row ^ swz4(d + 2))] = v.z;
        QsT[(d + 3) * 132 + (row ^ swz4(d + 3))] = v.w;
    }
    if (t < 128) rs[t] = 0.0f;
    __syncthreads();

    // ---------------- PASS 1: row sums of E = exp(relu(z/32)) --------------
    for (int jb = 0; jb < 8; jb++) {
        #pragma unroll
        for (int it = 0; it < 8; it++) {
            int fid = t + it * 256;
            int row = fid >> 4;
            int d   = (fid & 15) * 4;
            float4 v = *reinterpret_cast<const float4*>(&Kh[(size_t)(jb * 128 + row) * DPH + d]);
            KsT[(d + 0) * 132 + (row ^ swz4(d + 0))] = v.x;
            KsT[(d + 1) * 132 + (row ^ swz4(d + 1))] = v.y;
            KsT[(d + 2) * 132 + (row ^ swz4(d + 2))] = v.z;
            KsT[(d + 3) * 132 + (row ^ swz4(d + 3))] = v.w;
        }
        __syncthreads();

        float z[8][8];
        #pragma unroll
        for (int i = 0; i < 8; i++)
            #pragma unroll
            for (int j = 0; j < 8; j++) z[i][j] = 0.0f;

        #pragma unroll 8
        for (int d = 0; d < 64; d++) {
            int sw = swz4(d);
            const float* qrow = &QsT[d * 132];
            const float* krow = &KsT[d * 132];
            float4 a0 = *reinterpret_cast<const float4*>(&qrow[r0 ^ sw]);
            float4 a1 = *reinterpret_cast<const float4*>(&qrow[(64 + r0) ^ sw]);
            float4 b0 = *reinterpret_cast<const float4*>(&krow[c0 ^ sw]);
            float4 b1 = *reinterpret_cast<const float4*>(&krow[(64 + c0) ^ sw]);
            float a[8] = {a0.x, a0.y, a0.z, a0.w, a1.x, a1.y, a1.z, a1.w};
            float b[8] = {b0.x, b0.y, b0.z, b0.w, b1.x, b1.y, b1.z, b1.w};
            #pragma unroll
            for (int i = 0; i < 8; i++)
                #pragma unroll
                for (int j = 0; j < 8; j++) z[i][j] += a[i] * b[j];
        }

        #pragma unroll
        for (int i = 0; i < 8; i++) {
            float s = 0.0f;
            #pragma unroll
            for (int j = 0; j < 8; j++)
                s += __expf(fmaxf(z[i][j] * ATT_SCALE, 0.0f));
            int row = (i < 4) ? (r0 + i) : (64 + r0 + i - 4);
            atomicAdd(&rs[row], s);
        }
        __syncthreads();
    }

    float rinv[8];
    #pragma unroll
    for (int i = 0; i < 8; i++) {
        int row = (i < 4) ? (r0 + i) : (64 + r0 + i - 4);
        rinv[i] = 1.0f / rs[row];
    }

    // ---------------- PASS 2: P = E/rowsum, colsums, O = P @ V -------------
    float o[8][4];
    #pragma unroll
    for (int i = 0; i < 8; i++)
        #pragma unroll
        for (int c = 0; c < 4; c++) o[i][c] = 0.0f;

    for (int jb = 0; jb < 8; jb++) {
        #pragma unroll
        for (int it = 0; it < 8; it++) {
            int fid = t + it * 256;
            int row = fid >> 4;
            int d   = (fid & 15) * 4;
            float4 vk = *reinterpret_cast<const float4*>(&Kh[(size_t)(jb * 128 + row) * DPH + d]);
            KsT[(d + 0) * 132 + (row ^ swz4(d + 0))] = vk.x;
            KsT[(d + 1) * 132 + (row ^ swz4(d + 1))] = vk.y;
            KsT[(d + 2) * 132 + (row ^ swz4(d + 2))] = vk.z;
            KsT[(d + 3) * 132 + (row ^ swz4(d + 3))] = vk.w;
            float4 vv = *reinterpret_cast<const float4*>(&Vh[(size_t)(jb * 128 + row) * DPH + d]);
            *reinterpret_cast<float4*>(&Vs[row * 68 + d]) = vv;
        }
        if (t < 128) cs[t] = 0.0f;
        __syncthreads();

        float z[8][8];
        #pragma unroll
        for (int i = 0; i < 8; i++)
            #pragma unroll
            for (int j = 0; j < 8; j++) z[i][j] = 0.0f;

        #pragma unroll 8
        for (int d = 0; d < 64; d++) {
            int sw = swz4(d);
            const float* qrow = &QsT[d * 132];
            const float* krow = &KsT[d * 132];
            float4 a0 = *reinterpret_cast<const float4*>(&qrow[r0 ^ sw]);
            float4 a1 = *reinterpret_cast<const float4*>(&qrow[(64 + r0) ^ sw]);
            float4 b0 = *reinterpret_cast<const float4*>(&krow[c0 ^ sw]);
            float4 b1 = *reinterpret_cast<const float4*>(&krow[(64 + c0) ^ sw]);
            float a[8] = {a0.x, a0.y, a0.z, a0.w, a1.x, a1.y, a1.z, a1.w};
            float b[8] = {b0.x, b0.y, b0.z, b0.w, b1.x, b1.y, b1.z, b1.w};
            #pragma unroll
            for (int i = 0; i < 8; i++)
                #pragma unroll
                for (int j = 0; j < 8; j++) z[i][j] += a[i] * b[j];
        }

        #pragma unroll
        for (int j = 0; j < 8; j++) {
            int col = (j < 4) ? (c0 + j) : (64 + c0 + j - 4);
            int csw = swz4(col);
            float s = 0.0f;
            #pragma unroll
            for (int i = 0; i < 8; i++) {
                float p = __expf(fmaxf(z[i][j] * ATT_SCALE, 0.0f)) * rinv[i];
                s += p;
                int row = (i < 4) ? (r0 + i) : (64 + r0 + i - 4);
                PsT[col * 132 + (row ^ csw)] = p;
            }
            atomicAdd(&cs[col], s);
        }
        __syncthreads();

        #pragma unroll 4
        for (int j = 0; j < 128; j++) {
            int jsw = swz4(j);
            const float* prow = &PsT[j * 132];
            float4 pa = *reinterpret_cast<const float4*>(&prow[r0 ^ jsw]);
            float4 pb = *reinterpret_cast<const float4*>(&prow[(64 + r0) ^ jsw]);
            float4 vv = *reinterpret_cast<const float4*>(&Vs[j * 68 + c0]);
            float p[8] = {pa.x, pa.y, pa.z, pa.w, pb.x, pb.y, pb.z, pb.w};
            #pragma unroll
            for (int i = 0; i < 8; i++) {
                o[i][0] += p[i] * vv.x;
                o[i][1] += p[i] * vv.y;
                o[i][2] += p[i] * vv.z;
                o[i][3] += p[i] * vv.w;
            }
        }

        if (t < 128) atomicAdd(&sums[g * 1024 + jb * 128 + t], cs[t]);
        __syncthreads();
    }

    // write context
    float* __restrict__ Ch = g_ctx + (size_t)g * (SEQ * DPH);
    #pragma unroll
    for (int i = 0; i < 8; i++) {
        int row = ib * 128 + ((i < 4) ? (r0 + i) : (64 + r0 + i - 4));
        float4 ov; ov.x = o[i][0]; ov.y = o[i][1]; ov.z = o[i][2]; ov.w = o[i][3];
        *reinterpret_cast<float4*>(&Ch[(size_t)row * DPH + c0]) = ov;
    }
}

// ---------------------------------------------------------------------------
// Kernel 3: residual + LayerNorm.  One 256-thread CTA per row (4096 rows).
// ---------------------------------------------------------------------------
__global__ __launch_bounds__(256) void ln_kernel(
    const float* __restrict__ x,
    const float* __restrict__ gamma,
    const float* __restrict__ beta,
    float* __restrict__ out)
{
    const int row = blockIdx.x;
    const int t = threadIdx.x;
    const float* xr = x + (size_t)row * NTDIM;
    const float* cr = g_ctx + (size_t)row * NTDIM;

    float h[4];
    float s = 0.0f, sq = 0.0f;
    #pragma unroll
    for (int i = 0; i < 4; i++) {
        int idx = t + i * 256;
        h[i] = xr[idx] + cr[idx];
        s  += h[i];
        sq += h[i] * h[i];
    }
    #pragma unroll
    for (int off = 16; off; off >>= 1) {
        s  += __shfl_xor_sync(0xffffffffu, s,  off);
        sq += __shfl_xor_sync(0xffffffffu, sq, off);
    }
    __shared__ float rsum[8], rsq[8];
    int warp = t >> 5, lane = t & 31;
    if (lane == 0) { rsum[warp] = s; rsq[warp] = sq; }
    __syncthreads();
    float S = 0.0f, SQ = 0.0f;
    #pragma unroll
    for (int w = 0; w < 8; w++) { S += rsum[w]; SQ += rsq[w]; }
    float mean = S * (1.0f / NTDIM);
    float var  = SQ * (1.0f / NTDIM) - mean * mean;
    float inv  = rsqrtf(var + LNEPS);
    float* orow = out + (size_t)row * NTDIM;
    #pragma unroll
    for (int i = 0; i < 4; i++) {
        int idx = t + i * 256;
        orow[idx] = (h[i] - mean) * inv * gamma[idx] + beta[idx];
    }
}

// ---------------------------------------------------------------------------
extern "C" void kernel_launch(void* const* d_in, const int* in_sizes, int n_in,
                              void* d_out, int out_size)
{
    const float* x     = (const float*)d_in[0];
    const float* Wq    = (const float*)d_in[1];
    const float* bq    = (const float*)d_in[2];
    const float* Wk    = (const float*)d_in[3];
    const float* bk    = (const float*)d_in[4];
    const float* Wv    = (const float*)d_in[5];
    const float* bv    = (const float*)d_in[6];
    const float* gamma = (const float*)d_in[7];
    const float* beta  = (const float*)d_in[8];

    float* out  = (float*)d_out;
    float* sums = out + (size_t)M_ROWS * NTDIM;   // [64,1024] at_sum_sum region

    cudaFuncSetAttribute(attn_kernel,
                         cudaFuncAttributeMaxDynamicSharedMemorySize,
                         ATT_SMEM_BYTES);

    zero_sums_kernel<<<256, 256>>>(sums);

    dim3 gq(8, 32, 3);
    qkv_kernel<<<gq, 256>>>(x, Wq, bq, Wk, bk, Wv, bv);

    dim3 ga(8, 64);
    attn_kernel<<<ga, 256, ATT_SMEM_BYTES>>>(sums);

    ln_kernel<<<M_ROWS, 256>>>(x, gamma, beta, out);
}